// round 1
// baseline (speedup 1.0000x reference)
#include <cuda_runtime.h>
#include <cstdint>

// Problem dims
#define S_LEN 2048
#define BATCH 128
#define EDIM  128
#define LDIM  128
#define GDIM  512   // 4*LDIM, gate order: f, i, g, o

typedef unsigned long long ull;

// 512 MB scratch for precomputed input projections xg[t][b][512] (bias-folded)
__device__ float g_xg[(size_t)S_LEN * BATCH * GDIM];

// ---------------- packed fp32x2 helpers ----------------
__device__ __forceinline__ ull pack2(float a, float b) {
    ull r;
    asm("mov.b64 %0, {%1, %2};" : "=l"(r) : "f"(a), "f"(b));
    return r;
}
__device__ __forceinline__ float lo32(ull v) {
    float a, b;
    asm("mov.b64 {%0, %1}, %2;" : "=f"(a), "=f"(b) : "l"(v));
    return a;
}
__device__ __forceinline__ float hi32(ull v) {
    float a, b;
    asm("mov.b64 {%0, %1}, %2;" : "=f"(a), "=f"(b) : "l"(v));
    return b;
}
#define FFMA2(acc, a, b) asm("fma.rn.f32x2 %0, %1, %2, %0;" : "+l"(acc) : "l"(a), "l"(b))

__device__ __forceinline__ float fast_sigmoid(float x) {
    return __fdividef(1.f, 1.f + __expf(-x));
}
__device__ __forceinline__ float fast_tanh(float x) {
    return __fdividef(2.f, 1.f + __expf(-2.f * x)) - 1.f;
}

// =====================================================================
// Kernel 1: xg = x @ Wi + (bi + bh)    [M=S*B=262144, N=512, K=128]
// 128x128 tile per block, 256 threads, full K resident in smem, FFMA2.
// =====================================================================
__global__ __launch_bounds__(256) void xg_gemm(
    const float* __restrict__ x,
    const float* __restrict__ Wi,
    const float* __restrict__ bi,
    const float* __restrict__ bh)
{
    extern __shared__ float sm[];
    float* As     = sm;                   // [k][m] 128x128 (transposed)
    float* Bs     = sm + 128 * 128;       // [k][n] 128x128
    float* bias_s = Bs + 128 * 128;       // [128]

    const int tid = threadIdx.x;
    const int bm  = blockIdx.x;           // M tile (2048)
    const int bn  = blockIdx.y;           // N tile (4)

    // ---- load A tile, transposed to As[k][m] ----
    {
        const int m0 = tid & 31;
        const int kc = tid >> 5;          // 0..7
        #pragma unroll
        for (int rc = 0; rc < 4; rc++) {
            const int cc = kc + rc * 8;   // k-chunk 0..31 (4 floats each)
            #pragma unroll
            for (int rm = 0; rm < 4; rm++) {
                const int m = m0 + rm * 32;
                float4 v = *(const float4*)(x + (size_t)(bm * 128 + m) * EDIM + cc * 4);
                const int k0 = cc * 4;
                As[(k0 + 0) * 128 + m] = v.x;
                As[(k0 + 1) * 128 + m] = v.y;
                As[(k0 + 2) * 128 + m] = v.z;
                As[(k0 + 3) * 128 + m] = v.w;
            }
        }
    }
    // ---- load B tile Bs[k][n] ----
    {
        const int nc = tid & 31;
        const int kr = tid >> 5;
        #pragma unroll
        for (int r = 0; r < 16; r++) {
            const int k = kr + r * 8;
            float4 v = *(const float4*)(Wi + (size_t)k * GDIM + bn * 128 + nc * 4);
            *(float4*)(Bs + k * 128 + nc * 4) = v;
        }
    }
    if (tid < 128) bias_s[tid] = bi[bn * 128 + tid] + bh[bn * 128 + tid];
    __syncthreads();

    const int tx = tid & 15;              // n sub-tile
    const int ty = tid >> 4;              // m sub-tile

    ull acc[4][8];
    #pragma unroll
    for (int p = 0; p < 4; p++)
        #pragma unroll
        for (int n = 0; n < 8; n++) acc[p][n] = 0ULL;

    const float4* As4 = (const float4*)As;
    const float4* Bs4 = (const float4*)Bs;

    #pragma unroll 4
    for (int k = 0; k < 128; k++) {
        float4 a0 = As4[k * 32 + ty * 2];
        float4 a1 = As4[k * 32 + ty * 2 + 1];
        float4 b0 = Bs4[k * 32 + tx * 2];
        float4 b1 = Bs4[k * 32 + tx * 2 + 1];
        ull ap[4];
        ap[0] = pack2(a0.x, a0.y);
        ap[1] = pack2(a0.z, a0.w);
        ap[2] = pack2(a1.x, a1.y);
        ap[3] = pack2(a1.z, a1.w);
        float bv[8] = {b0.x, b0.y, b0.z, b0.w, b1.x, b1.y, b1.z, b1.w};
        #pragma unroll
        for (int n = 0; n < 8; n++) {
            ull bd = pack2(bv[n], bv[n]);
            #pragma unroll
            for (int p = 0; p < 4; p++) FFMA2(acc[p][n], ap[p], bd);
        }
    }

    // ---- epilogue: add bias, store ----
    #pragma unroll
    for (int r = 0; r < 8; r++) {
        const int p  = r >> 1;
        const int hi = r & 1;
        float vals[8];
        #pragma unroll
        for (int n = 0; n < 8; n++) {
            float v = hi ? hi32(acc[p][n]) : lo32(acc[p][n]);
            vals[n] = v + bias_s[tx * 8 + n];
        }
        float* dst = g_xg + (size_t)(bm * 128 + ty * 8 + r) * GDIM + bn * 128 + tx * 8;
        *(float4*)(dst)     = make_float4(vals[0], vals[1], vals[2], vals[3]);
        *(float4*)(dst + 4) = make_float4(vals[4], vals[5], vals[6], vals[7]);
    }
}

// =====================================================================
// Kernel 2: persistent per-batch LSTM recurrence + classifier head.
// 128 blocks (1 batch each), 512 threads (1 gate-column each).
// Wh: rows 32..127 (96) register-resident, rows 0..31 (32) in smem.
// FFMA2 over k-pairs; h broadcast from smem as 16B vectors.
// =====================================================================
#define REG_Q  24   // 24 quads -> 96 k-rows in registers
#define SM_Q   8    // 8 quads  -> 32 k-rows in smem

__global__ __launch_bounds__(512, 1) void lstm_rec(
    const float* __restrict__ Wh,
    const float* __restrict__ Wc,
    const float* __restrict__ bc,
    float* __restrict__ out)
{
    extern __shared__ char smraw[];
    ulonglong2* Ws = (ulonglong2*)smraw;                   // [SM_Q][512]
    float* h_s = (float*)(smraw + SM_Q * 512 * 16);        // [128], 16B aligned
    float* g_s = h_s + 128;                                // [512]

    const int j = threadIdx.x;   // gate column 0..511
    const int b = blockIdx.x;    // batch element

    // ---- stage Wh rows 0..31 into smem (k-quad packed per column) ----
    #pragma unroll
    for (int q = 0; q < SM_Q; q++) {
        const int k0 = 4 * q;
        float w0 = Wh[(k0 + 0) * GDIM + j];
        float w1 = Wh[(k0 + 1) * GDIM + j];
        float w2 = Wh[(k0 + 2) * GDIM + j];
        float w3 = Wh[(k0 + 3) * GDIM + j];
        ulonglong2 u;
        u.x = pack2(w0, w1);
        u.y = pack2(w2, w3);
        Ws[q * 512 + j] = u;
    }
    // ---- stage Wh rows 32..127 into registers ----
    ulonglong2 wr[REG_Q];
    #pragma unroll
    for (int q = 0; q < REG_Q; q++) {
        const int k0 = 4 * SM_Q + 4 * q;
        wr[q].x = pack2(Wh[(k0 + 0) * GDIM + j], Wh[(k0 + 1) * GDIM + j]);
        wr[q].y = pack2(Wh[(k0 + 2) * GDIM + j], Wh[(k0 + 3) * GDIM + j]);
    }

    if (j < 128) h_s[j] = 0.f;
    float c_val = 0.f;
    __syncthreads();

    const float* xgp = g_xg + (size_t)b * GDIM + j;
    const size_t stepStride = (size_t)BATCH * GDIM;
    float xg_c = __ldg(xgp);
    float xg_n = __ldg(xgp + stepStride);

    const ulonglong2* h4  = (const ulonglong2*)h_s;
    const ulonglong2* wsp = Ws + j;

    for (int t = 0; t < S_LEN; t++) {
        // prefetch xg for t+2 (covers ~2 step-times of DRAM latency)
        float xg_p = 0.f;
        if (t + 2 < S_LEN) xg_p = __ldg(xgp + (size_t)(t + 2) * stepStride);

        ull acc0 = 0ULL, acc1 = 0ULL;
        #pragma unroll
        for (int q = 0; q < SM_Q; q++) {
            ulonglong2 hv = h4[q];
            ulonglong2 wv = wsp[q * 512];
            FFMA2(acc0, wv.x, hv.x);
            FFMA2(acc1, wv.y, hv.y);
        }
        #pragma unroll
        for (int q = 0; q < REG_Q; q++) {
            ulonglong2 hv = h4[SM_Q + q];
            FFMA2(acc0, wr[q].x, hv.x);
            FFMA2(acc1, wr[q].y, hv.y);
        }
        float v = (lo32(acc0) + lo32(acc1)) + (hi32(acc0) + hi32(acc1)) + xg_c;
        xg_c = xg_n;
        xg_n = xg_p;

        const int gate = j >> 7;  // 0:f 1:i 2:g 3:o
        float act = (gate == 2) ? fast_tanh(v) : fast_sigmoid(v);
        g_s[j] = act;
        __syncthreads();

        if (j < 128) {
            float f  = g_s[j];
            float i_ = g_s[j + 128];
            float gt = g_s[j + 256];
            float o  = g_s[j + 384];
            c_val = f * c_val + i_ * gt;
            h_s[j] = o * fast_tanh(c_val);
        }
        __syncthreads();
    }

    // ---- classifier head: out[b][n] = h @ Wc + bc ----
    if (j < 2) {
        float s = __ldg(&bc[j]);
        #pragma unroll 8
        for (int l = 0; l < 128; l++) s += h_s[l] * __ldg(&Wc[l * 2 + j]);
        out[b * 2 + j] = s;
    }
}

// =====================================================================
extern "C" void kernel_launch(void* const* d_in, const int* in_sizes, int n_in,
                              void* d_out, int out_size)
{
    const float* x  = (const float*)d_in[0];
    const float* Wi = (const float*)d_in[1];
    const float* bi = (const float*)d_in[2];
    const float* Wh = (const float*)d_in[3];
    const float* bh = (const float*)d_in[4];
    const float* Wc = (const float*)d_in[5];
    const float* bc = (const float*)d_in[6];
    float* out = (float*)d_out;

    const int smemA = (128 * 128 * 2 + 128) * sizeof(float);              // 131584
    const int smemR = SM_Q * 512 * 16 + (128 + 512) * (int)sizeof(float); // 68096

    cudaFuncSetAttribute(xg_gemm,  cudaFuncAttributeMaxDynamicSharedMemorySize, smemA);
    cudaFuncSetAttribute(lstm_rec, cudaFuncAttributeMaxDynamicSharedMemorySize, smemR);

    dim3 gridA((S_LEN * BATCH) / 128, GDIM / 128);
    xg_gemm<<<gridA, 256, smemA>>>(x, Wi, bi, bh);
    lstm_rec<<<BATCH, 512, smemR>>>(Wh, Wc, bc, out);
}

// round 2
// speedup vs baseline: 1.1264x; 1.1264x over previous
#include <cuda_runtime.h>
#include <cstdint>

// Problem dims
#define S_LEN 2048
#define BATCH 128
#define EDIM  128
#define LDIM  128
#define GDIM  512   // 4*LDIM, gate order: f, i, g, o

typedef unsigned long long ull;

// 512 MB scratch for precomputed input projections xg[t][b][512] (bias-folded)
__device__ float g_xg[(size_t)S_LEN * BATCH * GDIM];

// ---------------- packed fp32x2 helpers ----------------
__device__ __forceinline__ ull pack2(float a, float b) {
    ull r;
    asm("mov.b64 %0, {%1, %2};" : "=l"(r) : "f"(a), "f"(b));
    return r;
}
__device__ __forceinline__ float lo32(ull v) {
    float a, b;
    asm("mov.b64 {%0, %1}, %2;" : "=f"(a), "=f"(b) : "l"(v));
    return a;
}
__device__ __forceinline__ float hi32(ull v) {
    float a, b;
    asm("mov.b64 {%0, %1}, %2;" : "=f"(a), "=f"(b) : "l"(v));
    return b;
}
#define FFMA2(acc, a, b) asm("fma.rn.f32x2 %0, %1, %2, %0;" : "+l"(acc) : "l"(a), "l"(b))

__device__ __forceinline__ float fast_sigmoid(float x) {
    return __fdividef(1.f, 1.f + __expf(-x));
}
__device__ __forceinline__ float fast_tanh(float x) {
    return __fdividef(2.f, 1.f + __expf(-2.f * x)) - 1.f;
}

// =====================================================================
// Kernel 1: xg = x @ Wi + (bi + bh)    [M=S*B=262144, N=512, K=128]
// 128x128 tile per block, 256 threads, full K resident in smem, FFMA2.
// (at fp32 FFMA2 roofline; unchanged this round)
// =====================================================================
__global__ __launch_bounds__(256) void xg_gemm(
    const float* __restrict__ x,
    const float* __restrict__ Wi,
    const float* __restrict__ bi,
    const float* __restrict__ bh)
{
    extern __shared__ float sm[];
    float* As     = sm;                   // [k][m] 128x128 (transposed)
    float* Bs     = sm + 128 * 128;       // [k][n] 128x128
    float* bias_s = Bs + 128 * 128;       // [128]

    const int tid = threadIdx.x;
    const int bm  = blockIdx.x;           // M tile (2048)
    const int bn  = blockIdx.y;           // N tile (4)

    {
        const int m0 = tid & 31;
        const int kc = tid >> 5;          // 0..7
        #pragma unroll
        for (int rc = 0; rc < 4; rc++) {
            const int cc = kc + rc * 8;
            #pragma unroll
            for (int rm = 0; rm < 4; rm++) {
                const int m = m0 + rm * 32;
                float4 v = *(const float4*)(x + (size_t)(bm * 128 + m) * EDIM + cc * 4);
                const int k0 = cc * 4;
                As[(k0 + 0) * 128 + m] = v.x;
                As[(k0 + 1) * 128 + m] = v.y;
                As[(k0 + 2) * 128 + m] = v.z;
                As[(k0 + 3) * 128 + m] = v.w;
            }
        }
    }
    {
        const int nc = tid & 31;
        const int kr = tid >> 5;
        #pragma unroll
        for (int r = 0; r < 16; r++) {
            const int k = kr + r * 8;
            float4 v = *(const float4*)(Wi + (size_t)k * GDIM + bn * 128 + nc * 4);
            *(float4*)(Bs + k * 128 + nc * 4) = v;
        }
    }
    if (tid < 128) bias_s[tid] = bi[bn * 128 + tid] + bh[bn * 128 + tid];
    __syncthreads();

    const int tx = tid & 15;
    const int ty = tid >> 4;

    ull acc[4][8];
    #pragma unroll
    for (int p = 0; p < 4; p++)
        #pragma unroll
        for (int n = 0; n < 8; n++) acc[p][n] = 0ULL;

    const float4* As4 = (const float4*)As;
    const float4* Bs4 = (const float4*)Bs;

    #pragma unroll 4
    for (int k = 0; k < 128; k++) {
        float4 a0 = As4[k * 32 + ty * 2];
        float4 a1 = As4[k * 32 + ty * 2 + 1];
        float4 b0 = Bs4[k * 32 + tx * 2];
        float4 b1 = Bs4[k * 32 + tx * 2 + 1];
        ull ap[4];
        ap[0] = pack2(a0.x, a0.y);
        ap[1] = pack2(a0.z, a0.w);
        ap[2] = pack2(a1.x, a1.y);
        ap[3] = pack2(a1.z, a1.w);
        float bv[8] = {b0.x, b0.y, b0.z, b0.w, b1.x, b1.y, b1.z, b1.w};
        #pragma unroll
        for (int n = 0; n < 8; n++) {
            ull bd = pack2(bv[n], bv[n]);
            #pragma unroll
            for (int p = 0; p < 4; p++) FFMA2(acc[p][n], ap[p], bd);
        }
    }

    #pragma unroll
    for (int r = 0; r < 8; r++) {
        const int p  = r >> 1;
        const int hi = r & 1;
        float vals[8];
        #pragma unroll
        for (int n = 0; n < 8; n++) {
            float v = hi ? hi32(acc[p][n]) : lo32(acc[p][n]);
            vals[n] = v + bias_s[tx * 8 + n];
        }
        float* dst = g_xg + (size_t)(bm * 128 + ty * 8 + r) * GDIM + bn * 128 + tx * 8;
        *(float4*)(dst)     = make_float4(vals[0], vals[1], vals[2], vals[3]);
        *(float4*)(dst + 4) = make_float4(vals[4], vals[5], vals[6], vals[7]);
    }
}

// =====================================================================
// Kernel 2: persistent per-batch LSTM recurrence + classifier head.
// 128 blocks (1 batch each), 256 threads, 2 gate-columns per thread:
//   thread p handles columns p (f or i) and p+256 (g or o).
// h-broadcast LDS shared across both columns (halves h wavefronts).
// Wh rows 32..127 register-resident for BOTH columns (192 regs),
// rows 0..31 streamed from smem. Cell state c lives in a register.
// =====================================================================
#define SM_Q   8    // 8 quads  -> rows 0..31 in smem
#define REG_Q  24   // 24 quads -> rows 32..127 in registers

__global__ __launch_bounds__(256, 1) void lstm_rec(
    const float* __restrict__ Wh,
    const float* __restrict__ Wc,
    const float* __restrict__ bc,
    float* __restrict__ out)
{
    extern __shared__ char smraw[];
    ulonglong2* Ws  = (ulonglong2*)smraw;                    // [SM_Q][512]
    float*  h_s  = (float*)(smraw + SM_Q * 512 * 16);        // [128], 16B aligned
    float2* io_s = (float2*)(h_s + 128);                     // [128] (i, o)

    const int p = threadIdx.x;     // 0..255
    const int b = blockIdx.x;      // batch element
    const int ca = p;              // column a: f (p<128) or i (p>=128)
    const int cb = p + 256;        // column b: g (p<128) or o (p>=128)

    // ---- stage Wh rows 0..31 into smem (k-quad packed per column) ----
    #pragma unroll
    for (int q = 0; q < SM_Q; q++) {
        const int k0 = 4 * q;
        #pragma unroll
        for (int s = 0; s < 2; s++) {
            const int col = p + s * 256;
            ulonglong2 u;
            u.x = pack2(__ldg(&Wh[(k0 + 0) * GDIM + col]), __ldg(&Wh[(k0 + 1) * GDIM + col]));
            u.y = pack2(__ldg(&Wh[(k0 + 2) * GDIM + col]), __ldg(&Wh[(k0 + 3) * GDIM + col]));
            Ws[q * 512 + col] = u;
        }
    }
    // ---- stage Wh rows 32..127 into registers for both columns ----
    ulonglong2 wra[REG_Q], wrb[REG_Q];
    #pragma unroll
    for (int q = 0; q < REG_Q; q++) {
        const int k0 = 4 * SM_Q + 4 * q;
        wra[q].x = pack2(__ldg(&Wh[(k0 + 0) * GDIM + ca]), __ldg(&Wh[(k0 + 1) * GDIM + ca]));
        wra[q].y = pack2(__ldg(&Wh[(k0 + 2) * GDIM + ca]), __ldg(&Wh[(k0 + 3) * GDIM + ca]));
        wrb[q].x = pack2(__ldg(&Wh[(k0 + 0) * GDIM + cb]), __ldg(&Wh[(k0 + 1) * GDIM + cb]));
        wrb[q].y = pack2(__ldg(&Wh[(k0 + 2) * GDIM + cb]), __ldg(&Wh[(k0 + 3) * GDIM + cb]));
    }

    if (p < 128) h_s[p] = 0.f;
    float c_val = 0.f;
    __syncthreads();

    const float* xga = g_xg + (size_t)b * GDIM + ca;
    const float* xgb = g_xg + (size_t)b * GDIM + cb;
    const size_t stepStride = (size_t)BATCH * GDIM;
    float xga_c = __ldg(xga);
    float xga_n = __ldg(xga + stepStride);
    float xgb_c = __ldg(xgb);
    float xgb_n = __ldg(xgb + stepStride);

    const ulonglong2* h4  = (const ulonglong2*)h_s;
    const ulonglong2* wsa = Ws + ca;
    const ulonglong2* wsb = Ws + cb;

    for (int t = 0; t < S_LEN; t++) {
        // prefetch xg for t+2 (covers DRAM latency across ~2 steps)
        float xga_p = 0.f, xgb_p = 0.f;
        if (t + 2 < S_LEN) {
            const size_t off = (size_t)(t + 2) * stepStride;
            xga_p = __ldg(xga + off);
            xgb_p = __ldg(xgb + off);
        }

        ull accA0 = 0ULL, accA1 = 0ULL, accB0 = 0ULL, accB1 = 0ULL;
        // rows 0..31 from smem
        #pragma unroll
        for (int q = 0; q < SM_Q; q++) {
            ulonglong2 hv = h4[q];
            ulonglong2 wa = wsa[q * 512];
            ulonglong2 wb = wsb[q * 512];
            FFMA2(accA0, wa.x, hv.x);
            FFMA2(accA1, wa.y, hv.y);
            FFMA2(accB0, wb.x, hv.x);
            FFMA2(accB1, wb.y, hv.y);
        }
        // rows 32..127 from registers
        #pragma unroll
        for (int q = 0; q < REG_Q; q++) {
            ulonglong2 hv = h4[SM_Q + q];
            FFMA2(accA0, wra[q].x, hv.x);
            FFMA2(accA1, wra[q].y, hv.y);
            FFMA2(accB0, wrb[q].x, hv.x);
            FFMA2(accB1, wrb[q].y, hv.y);
        }
        float va = (lo32(accA0) + lo32(accA1)) + (hi32(accA0) + hi32(accA1)) + xga_c;
        float vb = (lo32(accB0) + lo32(accB1)) + (hi32(accB0) + hi32(accB1)) + xgb_c;
        xga_c = xga_n; xga_n = xga_p;
        xgb_c = xgb_n; xgb_n = xgb_p;

        float f_act = 0.f, g_act = 0.f;
        if (p < 128) {
            f_act = fast_sigmoid(va);   // forget gate
            g_act = fast_tanh(vb);      // cell candidate
        } else {
            // (i, o) gates -> exchange via smem
            io_s[p - 128] = make_float2(fast_sigmoid(va), fast_sigmoid(vb));
        }
        __syncthreads();

        if (p < 128) {
            float2 io = io_s[p];
            c_val = f_act * c_val + io.x * g_act;
            h_s[p] = io.y * fast_tanh(c_val);
        }
        __syncthreads();
    }

    // ---- classifier head: out[b][n] = h @ Wc + bc ----
    if (p < 2) {
        float s = __ldg(&bc[p]);
        #pragma unroll 8
        for (int l = 0; l < 128; l++) s += h_s[l] * __ldg(&Wc[l * 2 + p]);
        out[b * 2 + p] = s;
    }
}

// =====================================================================
extern "C" void kernel_launch(void* const* d_in, const int* in_sizes, int n_in,
                              void* d_out, int out_size)
{
    const float* x  = (const float*)d_in[0];
    const float* Wi = (const float*)d_in[1];
    const float* bi = (const float*)d_in[2];
    const float* Wh = (const float*)d_in[3];
    const float* bh = (const float*)d_in[4];
    const float* Wc = (const float*)d_in[5];
    const float* bc = (const float*)d_in[6];
    float* out = (float*)d_out;

    const int smemA = (128 * 128 * 2 + 128) * sizeof(float);               // 131584
    const int smemR = SM_Q * 512 * 16 + 128 * (int)sizeof(float)
                    + 128 * (int)sizeof(float2);                           // 67072

    cudaFuncSetAttribute(xg_gemm,  cudaFuncAttributeMaxDynamicSharedMemorySize, smemA);
    cudaFuncSetAttribute(lstm_rec, cudaFuncAttributeMaxDynamicSharedMemorySize, smemR);

    dim3 gridA((S_LEN * BATCH) / 128, GDIM / 128);
    xg_gemm<<<gridA, 256, smemA>>>(x, Wi, bi, bh);
    lstm_rec<<<BATCH, 256, smemR>>>(Wh, Wc, bc, out);
}

// round 5
// speedup vs baseline: 1.5945x; 1.4156x over previous
#include <cuda_runtime.h>
#include <cstdint>

// Problem dims
#define S_LEN 2048
#define BATCH 128
#define EDIM  128
#define LDIM  128
#define GDIM  512   // 4*LDIM, gate order: f, i, g, o

typedef unsigned long long ull;

// 512 MB scratch for precomputed input projections xg[t][b][512] (bias-folded)
__device__ float g_xg[(size_t)S_LEN * BATCH * GDIM];

// ---------------- packed fp32x2 helpers ----------------
__device__ __forceinline__ ull pack2(float a, float b) {
    ull r;
    asm("mov.b64 %0, {%1, %2};" : "=l"(r) : "f"(a), "f"(b));
    return r;
}
__device__ __forceinline__ float lo32(ull v) {
    float a, b;
    asm("mov.b64 {%0, %1}, %2;" : "=f"(a), "=f"(b) : "l"(v));
    return a;
}
__device__ __forceinline__ float hi32(ull v) {
    float a, b;
    asm("mov.b64 {%0, %1}, %2;" : "=f"(a), "=f"(b) : "l"(v));
    return b;
}
#define FFMA2(acc, a, b) asm("fma.rn.f32x2 %0, %1, %2, %0;" : "+l"(acc) : "l"(a), "l"(b))

// ---------------- fast activations via MUFU.TANH ----------------
__device__ __forceinline__ float fast_tanh(float x) {
    float y;
    asm("tanh.approx.f32 %0, %1;" : "=f"(y) : "f"(x));
    return y;
}
__device__ __forceinline__ float fast_sigmoid(float x) {
    return fmaf(0.5f, fast_tanh(0.5f * x), 0.5f);
}

// =====================================================================
// Kernel 1: xg = x @ Wi + (bi + bh) via tf32 mma.sync  (tensor pipe)
// [M=S*B=262144, N=512, K=128]; block tile 128x256, 256 threads,
// full K resident in smem (As 128x132, Bs 128x264 — conflict-free pads).
// 8 warps as 2(m) x 4(n); warp tile 64x64; m16n8k8 tf32 fragments.
// =====================================================================
__global__ __launch_bounds__(256) void xg_gemm_tf32(
    const float* __restrict__ x,
    const float* __restrict__ Wi,
    const float* __restrict__ bi,
    const float* __restrict__ bh)
{
    extern __shared__ float sm[];
    float* As     = sm;                    // [128][132] tf32 bits
    float* Bs     = sm + 128 * 132;        // [128][264] tf32 bits
    float* bias_s = Bs + 128 * 264;        // [256]

    const int tid = threadIdx.x;
    const int bm  = blockIdx.x;            // 2048 M tiles
    const int bn  = blockIdx.y;            // 2 N tiles

    // ---- load A tile (x), convert to tf32, coalesced + conflict-free ----
    {
        const int c  = 4 * (tid & 31);     // col 0..124
        const int r0 = tid >> 5;           // 0..7
        #pragma unroll
        for (int i = 0; i < 16; i++) {
            const int m = r0 + 8 * i;
            float4 v = *(const float4*)(x + (size_t)(bm * 128 + m) * EDIM + c);
            uint4 u;
            asm("cvt.rna.tf32.f32 %0, %1;" : "=r"(u.x) : "f"(v.x));
            asm("cvt.rna.tf32.f32 %0, %1;" : "=r"(u.y) : "f"(v.y));
            asm("cvt.rna.tf32.f32 %0, %1;" : "=r"(u.z) : "f"(v.z));
            asm("cvt.rna.tf32.f32 %0, %1;" : "=r"(u.w) : "f"(v.w));
            *(uint4*)(As + m * 132 + c) = u;
        }
    }
    // ---- load B tile (Wi cols bn*256..+255), convert to tf32 ----
    {
        const int c  = 4 * (tid & 63);     // col within tile 0..252
        const int k0 = tid >> 6;           // 0..3
        #pragma unroll
        for (int i = 0; i < 32; i++) {
            const int k = k0 + 4 * i;
            float4 v = *(const float4*)(Wi + (size_t)k * GDIM + bn * 256 + c);
            uint4 u;
            asm("cvt.rna.tf32.f32 %0, %1;" : "=r"(u.x) : "f"(v.x));
            asm("cvt.rna.tf32.f32 %0, %1;" : "=r"(u.y) : "f"(v.y));
            asm("cvt.rna.tf32.f32 %0, %1;" : "=r"(u.z) : "f"(v.z));
            asm("cvt.rna.tf32.f32 %0, %1;" : "=r"(u.w) : "f"(v.w));
            *(uint4*)(Bs + k * 264 + c) = u;
        }
    }
    bias_s[tid] = bi[bn * 256 + tid] + bh[bn * 256 + tid];
    __syncthreads();

    const int lane = tid & 31;
    const int w    = tid >> 5;
    const int mb   = (w & 1) * 64;         // warp m base
    const int nb   = (w >> 1) * 64;        // warp n base
    const int r    = lane >> 2;            // 0..7
    const int cq   = lane & 3;             // 0..3

    float acc[4][8][4];
    #pragma unroll
    for (int f = 0; f < 4; f++)
        #pragma unroll
        for (int g = 0; g < 8; g++)
            #pragma unroll
            for (int i = 0; i < 4; i++) acc[f][g][i] = 0.f;

    #pragma unroll 4
    for (int s = 0; s < 16; s++) {
        const int k0 = 8 * s;
        uint32_t a[4][4];
        #pragma unroll
        for (int f = 0; f < 4; f++) {
            const float* ap = As + (mb + f * 16 + r) * 132 + k0 + cq;
            a[f][0] = __float_as_uint(ap[0]);
            a[f][1] = __float_as_uint(ap[8 * 132]);
            a[f][2] = __float_as_uint(ap[4]);
            a[f][3] = __float_as_uint(ap[8 * 132 + 4]);
        }
        uint32_t b[8][2];
        #pragma unroll
        for (int g = 0; g < 8; g++) {
            const float* bp = Bs + (k0 + cq) * 264 + nb + g * 8 + r;
            b[g][0] = __float_as_uint(bp[0]);
            b[g][1] = __float_as_uint(bp[4 * 264]);
        }
        #pragma unroll
        for (int f = 0; f < 4; f++)
            #pragma unroll
            for (int g = 0; g < 8; g++)
                asm("mma.sync.aligned.m16n8k8.row.col.f32.tf32.tf32.f32 "
                    "{%0,%1,%2,%3}, {%4,%5,%6,%7}, {%8,%9}, {%0,%1,%2,%3};"
                    : "+f"(acc[f][g][0]), "+f"(acc[f][g][1]),
                      "+f"(acc[f][g][2]), "+f"(acc[f][g][3])
                    : "r"(a[f][0]), "r"(a[f][1]), "r"(a[f][2]), "r"(a[f][3]),
                      "r"(b[g][0]), "r"(b[g][1]));
    }

    // ---- epilogue: add bias, store float2 pairs ----
    #pragma unroll
    for (int f = 0; f < 4; f++) {
        const int mrow = bm * 128 + mb + f * 16 + r;
        #pragma unroll
        for (int g = 0; g < 8; g++) {
            const int ncol = nb + g * 8 + 2 * cq;
            const float b0 = bias_s[ncol];
            const float b1 = bias_s[ncol + 1];
            float* d0 = g_xg + (size_t)mrow * GDIM + bn * 256 + ncol;
            *(float2*)d0 = make_float2(acc[f][g][0] + b0, acc[f][g][1] + b1);
            float* d1 = d0 + (size_t)8 * GDIM;
            *(float2*)d1 = make_float2(acc[f][g][2] + b0, acc[f][g][3] + b1);
        }
    }
}

// =====================================================================
// Kernel 2: persistent per-batch LSTM recurrence + classifier head.
// 128 blocks (1 batch each), 256 threads, 2 gate-columns per thread:
//   thread p handles columns p (f or i) and p+256 (g or o).
// Wh rows 32..127 register-resident for BOTH columns (192 regs),
// rows 0..31 streamed from smem. Cell state c lives in a register.
// Activations via MUFU.TANH (short critical path).
// =====================================================================
#define SM_Q   8    // 8 quads  -> rows 0..31 in smem
#define REG_Q  24   // 24 quads -> rows 32..127 in registers

__global__ __launch_bounds__(256, 1) void lstm_rec(
    const float* __restrict__ Wh,
    const float* __restrict__ Wc,
    const float* __restrict__ bc,
    float* __restrict__ out)
{
    extern __shared__ char smraw[];
    ulonglong2* Ws  = (ulonglong2*)smraw;                    // [SM_Q][512]
    float*  h_s  = (float*)(smraw + SM_Q * 512 * 16);        // [128], 16B aligned
    float2* io_s = (float2*)(h_s + 128);                     // [128] (i, o)

    const int p = threadIdx.x;     // 0..255
    const int b = blockIdx.x;      // batch element
    const int ca = p;              // column a: f (p<128) or i (p>=128)
    const int cb = p + 256;        // column b: g (p<128) or o (p>=128)

    // ---- stage Wh rows 0..31 into smem (k-quad packed per column) ----
    #pragma unroll
    for (int q = 0; q < SM_Q; q++) {
        const int k0 = 4 * q;
        #pragma unroll
        for (int s = 0; s < 2; s++) {
            const int col = p + s * 256;
            ulonglong2 u;
            u.x = pack2(__ldg(&Wh[(k0 + 0) * GDIM + col]), __ldg(&Wh[(k0 + 1) * GDIM + col]));
            u.y = pack2(__ldg(&Wh[(k0 + 2) * GDIM + col]), __ldg(&Wh[(k0 + 3) * GDIM + col]));
            Ws[q * 512 + col] = u;
        }
    }
    // ---- stage Wh rows 32..127 into registers for both columns ----
    ulonglong2 wra[REG_Q], wrb[REG_Q];
    #pragma unroll
    for (int q = 0; q < REG_Q; q++) {
        const int k0 = 4 * SM_Q + 4 * q;
        wra[q].x = pack2(__ldg(&Wh[(k0 + 0) * GDIM + ca]), __ldg(&Wh[(k0 + 1) * GDIM + ca]));
        wra[q].y = pack2(__ldg(&Wh[(k0 + 2) * GDIM + ca]), __ldg(&Wh[(k0 + 3) * GDIM + ca]));
        wrb[q].x = pack2(__ldg(&Wh[(k0 + 0) * GDIM + cb]), __ldg(&Wh[(k0 + 1) * GDIM + cb]));
        wrb[q].y = pack2(__ldg(&Wh[(k0 + 2) * GDIM + cb]), __ldg(&Wh[(k0 + 3) * GDIM + cb]));
    }

    if (p < 128) h_s[p] = 0.f;
    float c_val = 0.f;
    __syncthreads();

    const float* xga = g_xg + (size_t)b * GDIM + ca;
    const float* xgb = g_xg + (size_t)b * GDIM + cb;
    const size_t stepStride = (size_t)BATCH * GDIM;
    float xga_c = __ldg(xga);
    float xga_n = __ldg(xga + stepStride);
    float xgb_c = __ldg(xgb);
    float xgb_n = __ldg(xgb + stepStride);

    const ulonglong2* h4  = (const ulonglong2*)h_s;
    const ulonglong2* wsa = Ws + ca;
    const ulonglong2* wsb = Ws + cb;

    for (int t = 0; t < S_LEN; t++) {
        // prefetch xg for t+2 (branch-free clamped index)
        const size_t off = (size_t)((t + 2 < S_LEN) ? (t + 2) : (S_LEN - 1)) * stepStride;
        const float xga_p = __ldg(xga + off);
        const float xgb_p = __ldg(xgb + off);

        ull accA0 = 0ULL, accA1 = 0ULL, accB0 = 0ULL, accB1 = 0ULL;
        // rows 0..31 from smem
        #pragma unroll
        for (int q = 0; q < SM_Q; q++) {
            ulonglong2 hv = h4[q];
            ulonglong2 wa = wsa[q * 512];
            ulonglong2 wb = wsb[q * 512];
            FFMA2(accA0, wa.x, hv.x);
            FFMA2(accA1, wa.y, hv.y);
            FFMA2(accB0, wb.x, hv.x);
            FFMA2(accB1, wb.y, hv.y);
        }
        // rows 32..127 from registers
        #pragma unroll
        for (int q = 0; q < REG_Q; q++) {
            ulonglong2 hv = h4[SM_Q + q];
            FFMA2(accA0, wra[q].x, hv.x);
            FFMA2(accA1, wra[q].y, hv.y);
            FFMA2(accB0, wrb[q].x, hv.x);
            FFMA2(accB1, wrb[q].y, hv.y);
        }
        float va = (lo32(accA0) + lo32(accA1)) + (hi32(accA0) + hi32(accA1)) + xga_c;
        float vb = (lo32(accB0) + lo32(accB1)) + (hi32(accB0) + hi32(accB1)) + xgb_c;
        xga_c = xga_n; xga_n = xga_p;
        xgb_c = xgb_n; xgb_n = xgb_p;

        float f_act = 0.f, g_act = 0.f;
        if (p < 128) {
            f_act = fast_sigmoid(va);   // forget gate
            g_act = fast_tanh(vb);      // cell candidate
        } else {
            // (i, o) gates -> exchange via smem
            io_s[p - 128] = make_float2(fast_sigmoid(va), fast_sigmoid(vb));
        }
        __syncthreads();

        if (p < 128) {
            float2 io = io_s[p];
            c_val = f_act * c_val + io.x * g_act;
            h_s[p] = io.y * fast_tanh(c_val);
        }
        __syncthreads();
    }

    // ---- classifier head: out[b][n] = h @ Wc + bc ----
    if (p < 2) {
        float s = __ldg(&bc[p]);
        #pragma unroll 8
        for (int l = 0; l < 128; l++) s += h_s[l] * __ldg(&Wc[l * 2 + p]);
        out[b * 2 + p] = s;
    }
}

// =====================================================================
extern "C" void kernel_launch(void* const* d_in, const int* in_sizes, int n_in,
                              void* d_out, int out_size)
{
    const float* x  = (const float*)d_in[0];
    const float* Wi = (const float*)d_in[1];
    const float* bi = (const float*)d_in[2];
    const float* Wh = (const float*)d_in[3];
    const float* bh = (const float*)d_in[4];
    const float* Wc = (const float*)d_in[5];
    const float* bc = (const float*)d_in[6];
    float* out = (float*)d_out;

    const int smemA = (128 * 132 + 128 * 264 + 256) * (int)sizeof(float);  // 203776
    const int smemR = SM_Q * 512 * 16 + 128 * (int)sizeof(float)
                    + 128 * (int)sizeof(float2);                           // 67072

    cudaFuncSetAttribute(xg_gemm_tf32, cudaFuncAttributeMaxDynamicSharedMemorySize, smemA);
    cudaFuncSetAttribute(lstm_rec,     cudaFuncAttributeMaxDynamicSharedMemorySize, smemR);

    dim3 gridA((S_LEN * BATCH) / 128, GDIM / 256);
    xg_gemm_tf32<<<gridA, 256, smemA>>>(x, Wi, bi, bh);
    lstm_rec<<<BATCH, 256, smemR>>>(Wh, Wc, bc, out);
}